// round 1
// baseline (speedup 1.0000x reference)
#include <cuda_runtime.h>
#include <cstdint>
#include <cstddef>

#define DEV_INLINE __device__ __forceinline__

// Problem shape (fixed by setup_inputs)
static constexpr int B  = 8;
static constexpr int T  = 4096;
static constexpr int D  = 1024;
static constexpr int M  = B * T;       // 32768
static constexpr int N2 = 2 * D;       // 2048
static constexpr int CHUNK = 64;
static constexpr int NCH   = T / CHUNK; // 64

// ---------------- scratch (static __device__ arrays; no runtime alloc) ----
__device__ float g_c [(size_t)M * D];      // 128 MB  per-step coefficient
__device__ float g_v [(size_t)M * D];      // 128 MB  per-step value
__device__ float g_xr[(size_t)M * D];      // 128 MB  tf32-rounded x
__device__ float g_wr[(size_t)D * N2];     // 8 MB    tf32-rounded W
__device__ float g_P [B * NCH * D];        // chunk products
__device__ float g_S [B * NCH * D];        // chunk local scans
__device__ float g_h0[B * NCH * D];        // chunk initial h

// ---------------- helpers --------------------------------------------------
DEV_INLINE float to_tf32(float x) {
    float r;
    asm("cvt.rna.tf32.f32 %0, %1;" : "=f"(r) : "f"(x));
    return r;
}

DEV_INLINE unsigned smem_u32(const void* p) {
    return (unsigned)__cvta_generic_to_shared(p);
}
DEV_INLINE void cp16(void* dst, const void* src) {
    asm volatile("cp.async.cg.shared.global [%0], [%1], 16;"
                 :: "r"(smem_u32(dst)), "l"(src));
}
DEV_INLINE void cp_commit() { asm volatile("cp.async.commit_group;"); }
template<int N> DEV_INLINE void cp_wait() {
    asm volatile("cp.async.wait_group %0;" :: "n"(N));
}

DEV_INLINE void mma_tf32(float acc[4], const unsigned a[4], unsigned b0, unsigned b1) {
    asm volatile(
        "mma.sync.aligned.m16n8k8.row.col.f32.tf32.tf32.f32 "
        "{%0,%1,%2,%3}, {%4,%5,%6,%7}, {%8,%9}, {%0,%1,%2,%3};\n"
        : "+f"(acc[0]), "+f"(acc[1]), "+f"(acc[2]), "+f"(acc[3])
        : "r"(a[0]), "r"(a[1]), "r"(a[2]), "r"(a[3]), "r"(b0), "r"(b1));
}

// c = sigmoid(-k), v = sigmoid(k) * g(ht);  g(x) = x+0.5 (x>=0) else sigmoid(x)
DEV_INLINE void gate_act(float ht, float kv, float& c, float& v) {
    float ek   = __expf(-fabsf(kv));
    float inv  = 1.0f / (1.0f + ek);    // sigmoid(|k|)
    float sneg = ek * inv;              // sigmoid(-|k|)
    float z    = (kv >= 0.f) ? inv  : sneg;   // sigmoid(k)
    c          = (kv >= 0.f) ? sneg : inv;    // sigmoid(-k)
    float eh   = __expf(-fabsf(ht));
    float gneg = eh / (1.0f + eh);      // sigmoid(ht) for ht<0
    float g    = (ht >= 0.f) ? (ht + 0.5f) : gneg;
    v = z * g;
}

// ---------------- K0: tf32 rounding passes ---------------------------------
__global__ void round_x_kernel(const float* __restrict__ in) {
    int i = blockIdx.x * blockDim.x + threadIdx.x;   // float4 index
    float4 u = reinterpret_cast<const float4*>(in)[i];
    u.x = to_tf32(u.x); u.y = to_tf32(u.y); u.z = to_tf32(u.z); u.w = to_tf32(u.w);
    reinterpret_cast<float4*>(g_xr)[i] = u;
}
__global__ void round_w_kernel(const float* __restrict__ in) {
    int i = blockIdx.x * blockDim.x + threadIdx.x;
    float4 u = reinterpret_cast<const float4*>(in)[i];
    u.x = to_tf32(u.x); u.y = to_tf32(u.y); u.z = to_tf32(u.z); u.w = to_tf32(u.w);
    reinterpret_cast<float4*>(g_wr)[i] = u;
}

// ---------------- K1: tf32 GEMM + fused gate activation --------------------
// CTA tile: 128 rows (m) x 64 paired columns. Computes h_tilde cols [nb,nb+64)
// and k cols [1024+nb, 1024+nb+64) in the same k-loop; epilogue pairs them in
// registers and writes c,v.
static constexpr int BM  = 128;
static constexpr int BNH = 64;
static constexpr int BK  = 16;
static constexpr int APAD = 4;  // A row stride 20 floats (conflict-free frags)
static constexpr int BPAD = 8;  // B row stride 136 floats (conflict-free frags)

__global__ __launch_bounds__(256)
void gemm_gate_kernel(const float* __restrict__ bias) {
    __shared__ float As[2][BM][BK + APAD];        // 2*128*20*4  = 20.5 KB
    __shared__ float Bs[2][BK][2 * BNH + BPAD];   // 2*16*136*4  = 17.4 KB

    const int tid  = threadIdx.x;
    const int wid  = tid >> 5;
    const int lane = tid & 31;
    const int warp_m = wid & 3;          // 4 M sub-tiles of 32 rows
    const int warp_n = wid >> 2;         // 2 N sub-tiles of 32 cols (per half)
    const int qr = lane >> 2, qc = lane & 3;

    const int mb = blockIdx.y * BM;
    const int nb = blockIdx.x * BNH;

    const float* Aptr = g_xr + (size_t)mb * D;
    const float* Bptr = g_wr;

    float acc[2][2][4][4];
    #pragma unroll
    for (int a = 0; a < 2; a++)
        #pragma unroll
        for (int h = 0; h < 2; h++)
            #pragma unroll
            for (int n = 0; n < 4; n++)
                #pragma unroll
                for (int j = 0; j < 4; j++) acc[a][h][n][j] = 0.f;

    auto load_stage = [&](int s, int k0) {
        #pragma unroll
        for (int r = 0; r < 2; r++) {
            int id = tid + r * 256;                    // 0..511
            // A: 128 rows x 4 chunks of 16B
            int arow = id >> 2, ac = id & 3;
            cp16(&As[s][arow][ac * 4],
                 Aptr + (size_t)arow * D + k0 + ac * 4);
            // B: 16 k-rows x (2 halves x 16 chunks)
            int bk = id >> 5, bh = (id >> 4) & 1, bj = id & 15;
            cp16(&Bs[s][bk][bh * 64 + bj * 4],
                 Bptr + (size_t)(k0 + bk) * N2 + bh * D + nb + bj * 4);
        }
    };

    load_stage(0, 0);
    cp_commit();

    const int KT = D / BK;   // 64
    for (int ks = 0; ks < KT; ks++) {
        const int s = ks & 1;
        if (ks + 1 < KT) {
            load_stage(s ^ 1, (ks + 1) * BK);
            cp_commit();
            cp_wait<1>();
        } else {
            cp_wait<0>();
        }
        __syncthreads();

        #pragma unroll
        for (int kk = 0; kk < BK / 8; kk++) {
            unsigned a[2][4];
            #pragma unroll
            for (int mt = 0; mt < 2; mt++) {
                int r = warp_m * 32 + mt * 16 + qr;
                a[mt][0] = __float_as_uint(As[s][r    ][kk * 8 + qc    ]);
                a[mt][1] = __float_as_uint(As[s][r + 8][kk * 8 + qc    ]);
                a[mt][2] = __float_as_uint(As[s][r    ][kk * 8 + qc + 4]);
                a[mt][3] = __float_as_uint(As[s][r + 8][kk * 8 + qc + 4]);
            }
            #pragma unroll
            for (int h = 0; h < 2; h++) {
                #pragma unroll
                for (int nt = 0; nt < 4; nt++) {
                    int cidx = h * 64 + warp_n * 32 + nt * 8 + qr;
                    unsigned b0 = __float_as_uint(Bs[s][kk * 8 + qc    ][cidx]);
                    unsigned b1 = __float_as_uint(Bs[s][kk * 8 + qc + 4][cidx]);
                    mma_tf32(acc[0][h][nt], a[0], b0, b1);
                    mma_tf32(acc[1][h][nt], a[1], b0, b1);
                }
            }
        }
        __syncthreads();
    }

    // Epilogue: pair (h_tilde, k), apply gates, write c,v
    #pragma unroll
    for (int mt = 0; mt < 2; mt++) {
        #pragma unroll
        for (int j2 = 0; j2 < 2; j2++) {
            int r = mb + warp_m * 32 + mt * 16 + qr + j2 * 8;
            #pragma unroll
            for (int nt = 0; nt < 4; nt++) {
                int col = nb + warp_n * 32 + nt * 8 + qc * 2;
                float ht0 = acc[mt][0][nt][j2 * 2 + 0] + bias[col];
                float ht1 = acc[mt][0][nt][j2 * 2 + 1] + bias[col + 1];
                float kk0 = acc[mt][1][nt][j2 * 2 + 0] + bias[D + col];
                float kk1 = acc[mt][1][nt][j2 * 2 + 1] + bias[D + col + 1];
                float c0, v0, c1, v1;
                gate_act(ht0, kk0, c0, v0);
                gate_act(ht1, kk1, c1, v1);
                size_t o = (size_t)r * D + col;
                *reinterpret_cast<float2*>(g_c + o) = make_float2(c0, c1);
                *reinterpret_cast<float2*>(g_v + o) = make_float2(v0, v1);
            }
        }
    }
}

// ---------------- K2: per-chunk summaries (P = prod c, S = local scan) -----
__global__ __launch_bounds__(1024)
void chunk_summary_kernel() {
    int bc = blockIdx.x;             // b*NCH + chunk
    int d  = threadIdx.x;
    int b  = bc / NCH, ch = bc % NCH;
    size_t base = ((size_t)b * T + (size_t)ch * CHUNK) * D + d;
    float P = 1.f, S = 0.f;
    #pragma unroll 8
    for (int i = 0; i < CHUNK; i++) {
        float c = g_c[base + (size_t)i * D];
        float v = g_v[base + (size_t)i * D];
        S = fmaf(c, S, v);
        P *= c;
    }
    g_P[bc * D + d] = P;
    g_S[bc * D + d] = S;
}

// ---------------- K3: sequential scan across chunks ------------------------
__global__ __launch_bounds__(1024)
void chunk_scan_kernel() {
    int b = blockIdx.x;
    int d = threadIdx.x;
    float h = 0.f;
    for (int ch = 0; ch < NCH; ch++) {
        int idx = (b * NCH + ch) * D + d;
        g_h0[idx] = h;
        h = fmaf(g_P[idx], h, g_S[idx]);
    }
}

// ---------------- K4: apply scan + residual + LayerNorm --------------------
__global__ __launch_bounds__(1024)
void apply_ln_kernel(const float* __restrict__ x,
                     const float* __restrict__ gamma,
                     const float* __restrict__ beta,
                     float* __restrict__ out) {
    __shared__ float red[64];   // [0:32) sums, [32:64) sumsqs
    int bc = blockIdx.x;
    int d  = threadIdx.x;
    int b  = bc / NCH, ch = bc % NCH;
    int lane = d & 31, w = d >> 5;

    float h   = g_h0[bc * D + d];
    float gam = gamma[d];
    float bet = beta[d];
    size_t base = ((size_t)b * T + (size_t)ch * CHUNK) * D;

    for (int i = 0; i < CHUNK; i++) {
        size_t idx = base + (size_t)i * D + d;
        h = fmaf(g_c[idx], h, g_v[idx]);
        float y  = x[idx] + h;
        float s  = y;
        float sq = y * y;
        #pragma unroll
        for (int o = 16; o > 0; o >>= 1) {
            s  += __shfl_xor_sync(0xffffffffu, s,  o);
            sq += __shfl_xor_sync(0xffffffffu, sq, o);
        }
        if (lane == 0) { red[w] = s; red[32 + w] = sq; }
        __syncthreads();
        if (w == 0) {
            float s2 = red[lane];
            float q2 = red[32 + lane];
            #pragma unroll
            for (int o = 16; o > 0; o >>= 1) {
                s2 += __shfl_xor_sync(0xffffffffu, s2, o);
                q2 += __shfl_xor_sync(0xffffffffu, q2, o);
            }
            if (lane == 0) { red[0] = s2; red[32] = q2; }
        }
        __syncthreads();
        float mu  = red[0]  * (1.0f / D);
        float var = red[32] * (1.0f / D) - mu * mu;
        float inv = rsqrtf(var + 1e-6f);
        out[idx] = (y - mu) * inv * gam + bet;
        __syncthreads();   // red reused next iteration
    }
}

// ---------------- launch ----------------------------------------------------
extern "C" void kernel_launch(void* const* d_in, const int* in_sizes, int n_in,
                              void* d_out, int out_size) {
    const float* x     = (const float*)d_in[0];   // [8,4096,1024]
    const float* W     = (const float*)d_in[1];   // [1024,2048]
    const float* bias  = (const float*)d_in[2];   // [2048]
    const float* gamma = (const float*)d_in[3];   // [1024]
    const float* beta  = (const float*)d_in[4];   // [1024]
    float* out = (float*)d_out;

    (void)in_sizes; (void)n_in; (void)out_size;

    // K0: tf32-RNE rounding of GEMM operands
    {
        int n4x = (M * D) / 4;          // 8388608
        round_x_kernel<<<n4x / 256, 256>>>(x);
        int n4w = (D * N2) / 4;         // 524288
        round_w_kernel<<<n4w / 256, 256>>>(W);
    }

    // K1: GEMM + gate activation
    {
        dim3 grid(D / BNH, M / BM);     // (16, 256)
        gemm_gate_kernel<<<grid, 256>>>(bias);
    }

    // K2: chunk summaries
    chunk_summary_kernel<<<B * NCH, D>>>();

    // K3: cross-chunk scan
    chunk_scan_kernel<<<B, D>>>();

    // K4: apply + residual + LayerNorm
    apply_ln_kernel<<<B * NCH, D>>>(x, gamma, beta, out);
}

// round 3
// speedup vs baseline: 1.2489x; 1.2489x over previous
#include <cuda_runtime.h>
#include <cstdint>
#include <cstddef>

#define DEV_INLINE __device__ __forceinline__

// Problem shape (fixed by setup_inputs)
static constexpr int B  = 8;
static constexpr int T  = 4096;
static constexpr int D  = 1024;
static constexpr int M  = B * T;       // 32768
static constexpr int N2 = 2 * D;       // 2048
static constexpr int CHUNK = 64;
static constexpr int NCH   = T / CHUNK; // 64

// ---------------- scratch (static __device__ arrays) -----------------------
__device__ float g_c [(size_t)M * D];      // per-step coefficient
__device__ float g_v [(size_t)M * D];      // per-step value
__device__ float g_wt[(size_t)N2 * D];     // transposed + tf32-rounded W  [n][k]
__device__ float g_P [B * NCH * D];
__device__ float g_S [B * NCH * D];
__device__ float g_h0[B * NCH * D];

// ---------------- helpers --------------------------------------------------
DEV_INLINE float to_tf32(float x) {
    float r;
    asm("cvt.rna.tf32.f32 %0, %1;" : "=f"(r) : "f"(x));
    return r;
}
DEV_INLINE uint32_t tf32r(uint32_t u) {
    float r;
    asm("cvt.rna.tf32.f32 %0, %1;" : "=f"(r) : "f"(__uint_as_float(u)));
    return __float_as_uint(r);
}
DEV_INLINE unsigned smem_u32(const void* p) {
    return (unsigned)__cvta_generic_to_shared(p);
}
DEV_INLINE void cp16(unsigned dst, const void* src) {
    asm volatile("cp.async.cg.shared.global [%0], [%1], 16;"
                 :: "r"(dst), "l"(src));
}
DEV_INLINE void cp_commit() { asm volatile("cp.async.commit_group;"); }
template<int N> DEV_INLINE void cp_wait() {
    asm volatile("cp.async.wait_group %0;" :: "n"(N));
}

DEV_INLINE void ldsm_x4(uint32_t r[4], unsigned addr) {
    asm volatile("ldmatrix.sync.aligned.m8n8.x4.shared.b16 {%0,%1,%2,%3}, [%4];"
                 : "=r"(r[0]), "=r"(r[1]), "=r"(r[2]), "=r"(r[3]) : "r"(addr));
}

DEV_INLINE void mma_tf32(float acc[4], const uint32_t a[4], uint32_t b0, uint32_t b1) {
    asm volatile(
        "mma.sync.aligned.m16n8k8.row.col.f32.tf32.tf32.f32 "
        "{%0,%1,%2,%3}, {%4,%5,%6,%7}, {%8,%9}, {%0,%1,%2,%3};\n"
        : "+f"(acc[0]), "+f"(acc[1]), "+f"(acc[2]), "+f"(acc[3])
        : "r"(a[0]), "r"(a[1]), "r"(a[2]), "r"(a[3]), "r"(b0), "r"(b1));
}

// c = sigmoid(-k), v = sigmoid(k) * g(ht);  g(x) = x+0.5 (x>=0) else sigmoid(x)
DEV_INLINE void gate_act(float ht, float kv, float& c, float& v) {
    float ek   = __expf(-fabsf(kv));
    float inv  = 1.0f / (1.0f + ek);
    float sneg = ek * inv;
    float z    = (kv >= 0.f) ? inv  : sneg;
    c          = (kv >= 0.f) ? sneg : inv;
    float eh   = __expf(-fabsf(ht));
    float gneg = eh / (1.0f + eh);
    float g    = (ht >= 0.f) ? (ht + 0.5f) : gneg;
    v = z * g;
}

// ---------------- K0: transpose + round W: g_wt[n][k] = tf32(W[k][n]) ------
__global__ void transpose_w_kernel(const float* __restrict__ Wm) {
    __shared__ float t[32][33];
    int n0 = blockIdx.x * 32, k0 = blockIdx.y * 32;
    int tx = threadIdx.x, ty = threadIdx.y;
    #pragma unroll
    for (int i = ty; i < 32; i += 8)
        t[i][tx] = to_tf32(Wm[(size_t)(k0 + i) * N2 + n0 + tx]);
    __syncthreads();
    #pragma unroll
    for (int j = ty; j < 32; j += 8)
        g_wt[(size_t)(n0 + j) * D + k0 + tx] = t[tx][j];
}

// ---------------- K1: tf32 mma.sync GEMM + fused gate activation -----------
// CTA tile: 128 m-rows x 128 paired cols (h col j and k col D+j together).
// B smem rows 0..127 = h cols [nb, nb+128), rows 128..255 = k cols.
// 8 warps: warp_m in {0,1} (64 rows), warp_n in {0..3} (32 paired cols).
// BK=32 (128B rows, SW128 swizzle), 4-stage cp.async pipeline, ldmatrix frags.
static constexpr int BM = 128;
static constexpr int BNP = 128;              // paired columns per CTA
static constexpr int BK = 32;
static constexpr int STAGES = 4;
static constexpr int KT = D / BK;            // 32
static constexpr int ASTAGE = BM * 128;              // 16 KB
static constexpr int BSTAGE = 2 * BNP * 128;         // 32 KB
static constexpr int STAGE_BYTES = ASTAGE + BSTAGE;  // 48 KB
static constexpr int SMEM_TOTAL = STAGES * STAGE_BYTES;  // 192 KB

__global__ __launch_bounds__(256, 1)
void gemm_gate_kernel(const float* __restrict__ x, const float* __restrict__ bias) {
    extern __shared__ __align__(1024) unsigned char smem_buf[];
    const unsigned sbase = smem_u32(smem_buf);
    const int tid  = threadIdx.x;
    const int wid  = tid >> 5;
    const int lane = tid & 31;
    const int warp_m = wid & 1;
    const int warp_n = wid >> 1;
    const int qr = lane >> 2, qc = lane & 3;

    const int mb = blockIdx.y * BM;
    const int nb = blockIdx.x * BNP;
    const float* xA = x + (size_t)mb * D;

    // ---- per-lane ldmatrix address components ----
    // A tiles: lanes 0-7 -> rows+0 (k lo), 8-15 -> rows+8 (k lo),
    //          16-23 -> rows+0 (k hi), 24-31 -> rows+8 (k hi)
    const unsigned rA7 = (unsigned)(lane & 7);
    const unsigned sXor = rA7 << 4;                    // swizzle XOR term
    const unsigned hA16 = (unsigned)(lane & 16);       // A: k-half select
    unsigned offA[4];
    #pragma unroll
    for (int mt = 0; mt < 4; mt++) {
        unsigned row = (unsigned)(warp_m * 64 + mt * 16) + rA7 + ((lane & 8) ? 8u : 0u);
        offA[mt] = row * 128u;
    }
    // B tiles: lanes 0-7 -> rows+0 (k lo), 8-15 -> rows+0 (k hi),
    //          16-23 -> rows+8 (k lo), 24-31 -> rows+8 (k hi)
    const unsigned hB16 = (unsigned)((lane & 8) << 1); // B: k-half select
    unsigned offBh[2], offBk[2];
    #pragma unroll
    for (int p = 0; p < 2; p++) {
        unsigned row = (unsigned)(warp_n * 32 + p * 16) + rA7 + ((lane & 16) ? 8u : 0u);
        offBh[p] = row * 128u;
        offBk[p] = offBh[p] + (unsigned)(BNP * 128);
    }

    float acc[4][8][4];
    #pragma unroll
    for (int mt = 0; mt < 4; mt++)
        #pragma unroll
        for (int nt = 0; nt < 8; nt++)
            #pragma unroll
            for (int j = 0; j < 4; j++) acc[mt][nt][j] = 0.f;

    auto load_stage = [&](int s, int kiter) {
        const int k0 = kiter * BK;
        const unsigned abase = sbase + (unsigned)s * STAGE_BYTES;
        const unsigned bbase = abase + ASTAGE;
        // A: 128 rows x 8 chunks of 16B
        #pragma unroll
        for (int i = 0; i < 4; i++) {
            int id = tid + i * 256;
            int r = id >> 3, c = id & 7;
            unsigned off = (unsigned)r * 128u + (((unsigned)c * 16u) ^ (((unsigned)r & 7u) << 4));
            cp16(abase + off, xA + (size_t)r * D + k0 + c * 4);
        }
        // B: 256 rows (128 h + 128 k) x 8 chunks
        #pragma unroll
        for (int i = 0; i < 8; i++) {
            int id = tid + i * 256;
            int r = id >> 3, c = id & 7;
            int wrow = (r < BNP) ? (nb + r) : (D + nb + (r - BNP));
            unsigned off = (unsigned)r * 128u + (((unsigned)c * 16u) ^ (((unsigned)r & 7u) << 4));
            cp16(bbase + off, g_wt + (size_t)wrow * D + k0 + c * 4);
        }
    };

    auto compute_stage = [&](int s) {
        const unsigned abase = sbase + (unsigned)s * STAGE_BYTES;
        const unsigned bbase = abase + ASTAGE;
        #pragma unroll
        for (int kk = 0; kk < 4; kk++) {
            const unsigned tA = (((unsigned)kk << 5) | hA16) ^ sXor;
            const unsigned tB = (((unsigned)kk << 5) | hB16) ^ sXor;
            uint32_t a[4][4];
            #pragma unroll
            for (int mt = 0; mt < 4; mt++) {
                ldsm_x4(a[mt], abase + offA[mt] + tA);
                a[mt][0] = tf32r(a[mt][0]); a[mt][1] = tf32r(a[mt][1]);
                a[mt][2] = tf32r(a[mt][2]); a[mt][3] = tf32r(a[mt][3]);
            }
            uint32_t bh[2][4], bk[2][4];
            #pragma unroll
            for (int p = 0; p < 2; p++) {
                ldsm_x4(bh[p], bbase + offBh[p] + tB);
                ldsm_x4(bk[p], bbase + offBk[p] + tB);
            }
            #pragma unroll
            for (int mt = 0; mt < 4; mt++) {
                #pragma unroll
                for (int p = 0; p < 2; p++) {
                    mma_tf32(acc[mt][p * 2    ], a[mt], bh[p][0], bh[p][1]);
                    mma_tf32(acc[mt][p * 2 + 1], a[mt], bh[p][2], bh[p][3]);
                    mma_tf32(acc[mt][4 + p * 2    ], a[mt], bk[p][0], bk[p][1]);
                    mma_tf32(acc[mt][4 + p * 2 + 1], a[mt], bk[p][2], bk[p][3]);
                }
            }
        }
    };

    // prologue: stages 0..2
    load_stage(0, 0); cp_commit();
    load_stage(1, 1); cp_commit();
    load_stage(2, 2); cp_commit();

    for (int ks = 0; ks < KT; ks++) {
        cp_wait<STAGES - 2>();
        __syncthreads();
        if (ks + STAGES - 1 < KT) load_stage((ks + STAGES - 1) % STAGES, ks + STAGES - 1);
        cp_commit();
        compute_stage(ks % STAGES);
    }

    // ---- epilogue: pair (h, k), apply gates, write c,v ----
    #pragma unroll
    for (int nt = 0; nt < 4; nt++) {
        const int col = nb + warp_n * 32 + nt * 8 + qc * 2;
        const float2 bh2 = *reinterpret_cast<const float2*>(bias + col);
        const float2 bk2 = *reinterpret_cast<const float2*>(bias + D + col);
        #pragma unroll
        for (int mt = 0; mt < 4; mt++) {
            #pragma unroll
            for (int j2 = 0; j2 < 2; j2++) {
                const int row = mb + warp_m * 64 + mt * 16 + qr + j2 * 8;
                float h0 = acc[mt][nt][j2 * 2 + 0] + bh2.x;
                float h1 = acc[mt][nt][j2 * 2 + 1] + bh2.y;
                float k0 = acc[mt][nt + 4][j2 * 2 + 0] + bk2.x;
                float k1 = acc[mt][nt + 4][j2 * 2 + 1] + bk2.y;
                float c0, v0, c1, v1;
                gate_act(h0, k0, c0, v0);
                gate_act(h1, k1, c1, v1);
                const size_t o = (size_t)row * D + col;
                *reinterpret_cast<float2*>(g_c + o) = make_float2(c0, c1);
                *reinterpret_cast<float2*>(g_v + o) = make_float2(v0, v1);
            }
        }
    }
}

// ---------------- K2: per-chunk summaries (float4) -------------------------
__global__ __launch_bounds__(256)
void chunk_summary_kernel() {
    int bc = blockIdx.x;             // b*NCH + chunk
    int d4 = threadIdx.x;            // 4 floats each
    int b  = bc / NCH, ch = bc % NCH;
    size_t base = ((size_t)b * T + (size_t)ch * CHUNK) * D + d4 * 4;
    float4 P = make_float4(1.f, 1.f, 1.f, 1.f);
    float4 S = make_float4(0.f, 0.f, 0.f, 0.f);
    #pragma unroll 4
    for (int i = 0; i < CHUNK; i++) {
        float4 c = *reinterpret_cast<const float4*>(g_c + base + (size_t)i * D);
        float4 v = *reinterpret_cast<const float4*>(g_v + base + (size_t)i * D);
        S.x = fmaf(c.x, S.x, v.x); S.y = fmaf(c.y, S.y, v.y);
        S.z = fmaf(c.z, S.z, v.z); S.w = fmaf(c.w, S.w, v.w);
        P.x *= c.x; P.y *= c.y; P.z *= c.z; P.w *= c.w;
    }
    *reinterpret_cast<float4*>(g_P + (size_t)bc * D + d4 * 4) = P;
    *reinterpret_cast<float4*>(g_S + (size_t)bc * D + d4 * 4) = S;
}

// ---------------- K3: sequential scan across chunks (prefetch depth 2) -----
__global__ __launch_bounds__(256)
void chunk_scan_kernel() {
    int b  = blockIdx.x;
    int d4 = threadIdx.x;
    size_t idx0 = (size_t)(b * NCH) * D + d4 * 4;
    float4 h  = make_float4(0.f, 0.f, 0.f, 0.f);
    float4 P0 = *reinterpret_cast<const float4*>(g_P + idx0);
    float4 S0 = *reinterpret_cast<const float4*>(g_S + idx0);
    float4 P1 = *reinterpret_cast<const float4*>(g_P + idx0 + D);
    float4 S1 = *reinterpret_cast<const float4*>(g_S + idx0 + D);
    for (int ch = 0; ch < NCH; ch++) {
        float4 Pn, Sn;
        if (ch + 2 < NCH) {
            Pn = *reinterpret_cast<const float4*>(g_P + idx0 + (size_t)(ch + 2) * D);
            Sn = *reinterpret_cast<const float4*>(g_S + idx0 + (size_t)(ch + 2) * D);
        }
        *reinterpret_cast<float4*>(g_h0 + idx0 + (size_t)ch * D) = h;
        h.x = fmaf(P0.x, h.x, S0.x); h.y = fmaf(P0.y, h.y, S0.y);
        h.z = fmaf(P0.z, h.z, S0.z); h.w = fmaf(P0.w, h.w, S0.w);
        P0 = P1; S0 = S1; P1 = Pn; S1 = Sn;
    }
}

// ---------------- K4: apply scan + residual + LayerNorm (float4+prefetch) --
__global__ __launch_bounds__(256)
void apply_ln_kernel(const float* __restrict__ x,
                     const float* __restrict__ gamma,
                     const float* __restrict__ beta,
                     float* __restrict__ out) {
    __shared__ float red[16];
    int bc = blockIdx.x;
    int tid = threadIdx.x;
    int b  = bc / NCH, ch = bc % NCH;
    int lane = tid & 31, w = tid >> 5;
    size_t d4 = (size_t)tid * 4;

    float4 h = *reinterpret_cast<const float4*>(g_h0 + (size_t)bc * D + d4);
    float4 gm = *reinterpret_cast<const float4*>(gamma + d4);
    float4 bt = *reinterpret_cast<const float4*>(beta + d4);
    size_t base = ((size_t)b * T + (size_t)ch * CHUNK) * D + d4;

    float4 c4 = *reinterpret_cast<const float4*>(g_c + base);
    float4 v4 = *reinterpret_cast<const float4*>(g_v + base);
    float4 x4 = *reinterpret_cast<const float4*>(x + base);

    for (int i = 0; i < CHUNK; i++) {
        float4 cn, vn, xn;
        if (i + 1 < CHUNK) {
            size_t nb2 = base + (size_t)(i + 1) * D;
            cn = *reinterpret_cast<const float4*>(g_c + nb2);
            vn = *reinterpret_cast<const float4*>(g_v + nb2);
            xn = *reinterpret_cast<const float4*>(x + nb2);
        }
        h.x = fmaf(c4.x, h.x, v4.x); h.y = fmaf(c4.y, h.y, v4.y);
        h.z = fmaf(c4.z, h.z, v4.z); h.w = fmaf(c4.w, h.w, v4.w);
        float4 y;
        y.x = x4.x + h.x; y.y = x4.y + h.y; y.z = x4.z + h.z; y.w = x4.w + h.w;
        float s  = y.x + y.y + y.z + y.w;
        float sq = y.x * y.x + y.y * y.y + y.z * y.z + y.w * y.w;
        #pragma unroll
        for (int o = 16; o > 0; o >>= 1) {
            s  += __shfl_xor_sync(0xffffffffu, s,  o);
            sq += __shfl_xor_sync(0xffffffffu, sq, o);
        }
        if (lane == 0) { red[w] = s; red[8 + w] = sq; }
        __syncthreads();
        if (tid == 0) {
            float s2 = 0.f, q2 = 0.f;
            #pragma unroll
            for (int k = 0; k < 8; k++) { s2 += red[k]; q2 += red[8 + k]; }
            red[0] = s2; red[8] = q2;
        }
        __syncthreads();
        float mu  = red[0] * (1.0f / D);
        float var = red[8] * (1.0f / D) - mu * mu;
        float inv = rsqrtf(var + 1e-6f);
        float4 o4;
        o4.x = (y.x - mu) * inv * gm.x + bt.x;
        o4.y = (y.y - mu) * inv * gm.y + bt.y;
        o4.z = (y.z - mu) * inv * gm.z + bt.z;
        o4.w = (y.w - mu) * inv * gm.w + bt.w;
        *reinterpret_cast<float4*>(out + base + (size_t)i * D) = o4;
        c4 = cn; v4 = vn; x4 = xn;
        __syncthreads();   // red reuse
    }
}

// ---------------- launch ----------------------------------------------------
extern "C" void kernel_launch(void* const* d_in, const int* in_sizes, int n_in,
                              void* d_out, int out_size) {
    const float* x     = (const float*)d_in[0];
    const float* W     = (const float*)d_in[1];
    const float* bias  = (const float*)d_in[2];
    const float* gamma = (const float*)d_in[3];
    const float* beta  = (const float*)d_in[4];
    float* out = (float*)d_out;
    (void)in_sizes; (void)n_in; (void)out_size;

    // K0: transpose + tf32-round W
    transpose_w_kernel<<<dim3(N2 / 32, D / 32), dim3(32, 8)>>>(W);

    // K1: tf32 mma.sync GEMM + gates
    static bool attr_set = false;
    if (!attr_set) {
        cudaFuncSetAttribute(gemm_gate_kernel,
                             cudaFuncAttributeMaxDynamicSharedMemorySize, SMEM_TOTAL);
        attr_set = true;
    }
    gemm_gate_kernel<<<dim3(D / BNP, M / BM), 256, SMEM_TOTAL>>>(x, bias);

    // K2: chunk summaries
    chunk_summary_kernel<<<B * NCH, 256>>>();

    // K3: cross-chunk scan
    chunk_scan_kernel<<<B, 256>>>();

    // K4: apply + residual + LayerNorm
    apply_ln_kernel<<<B * NCH, 256>>>(x, gamma, beta, out);
}

// round 4
// speedup vs baseline: 1.9381x; 1.5519x over previous
#include <cuda_runtime.h>
#include <cuda_fp16.h>
#include <cstdint>
#include <cstddef>

#define DEV_INLINE __device__ __forceinline__

// Problem shape (fixed by setup_inputs)
static constexpr int B  = 8;
static constexpr int T  = 4096;
static constexpr int D  = 1024;
static constexpr int M  = B * T;       // 32768
static constexpr int N2 = 2 * D;       // 2048
static constexpr int CHUNK = 64;
static constexpr int NCH   = T / CHUNK; // 64

// ---------------- scratch (static __device__ arrays) -----------------------
__device__ float  g_c [(size_t)M * D];     // per-step coefficient
__device__ float  g_v [(size_t)M * D];     // per-step value
__device__ __half g_xh[(size_t)M * D];     // fp16 x
__device__ __half g_wh[(size_t)N2 * D];    // fp16 transposed W  [n][k]
__device__ float  g_P [B * NCH * D];
__device__ float  g_S [B * NCH * D];
__device__ float  g_h0[B * NCH * D];

// ---------------- helpers --------------------------------------------------
DEV_INLINE unsigned smem_u32(const void* p) {
    return (unsigned)__cvta_generic_to_shared(p);
}
DEV_INLINE void cp16(unsigned dst, const void* src) {
    asm volatile("cp.async.cg.shared.global [%0], [%1], 16;"
                 :: "r"(dst), "l"(src));
}
DEV_INLINE void cp_commit() { asm volatile("cp.async.commit_group;"); }
template<int N> DEV_INLINE void cp_wait() {
    asm volatile("cp.async.wait_group %0;" :: "n"(N));
}

DEV_INLINE void ldsm_x4(uint32_t r[4], unsigned addr) {
    asm volatile("ldmatrix.sync.aligned.m8n8.x4.shared.b16 {%0,%1,%2,%3}, [%4];"
                 : "=r"(r[0]), "=r"(r[1]), "=r"(r[2]), "=r"(r[3]) : "r"(addr));
}

DEV_INLINE void mma_f16(float acc[4], const uint32_t a[4], uint32_t b0, uint32_t b1) {
    asm volatile(
        "mma.sync.aligned.m16n8k16.row.col.f32.f16.f16.f32 "
        "{%0,%1,%2,%3}, {%4,%5,%6,%7}, {%8,%9}, {%0,%1,%2,%3};\n"
        : "+f"(acc[0]), "+f"(acc[1]), "+f"(acc[2]), "+f"(acc[3])
        : "r"(a[0]), "r"(a[1]), "r"(a[2]), "r"(a[3]), "r"(b0), "r"(b1));
}

// c = sigmoid(-k), v = sigmoid(k) * g(ht);  g(x) = x+0.5 (x>=0) else sigmoid(x)
DEV_INLINE void gate_act(float ht, float kv, float& c, float& v) {
    float ek   = __expf(-fabsf(kv));
    float inv  = 1.0f / (1.0f + ek);
    float sneg = ek * inv;
    float z    = (kv >= 0.f) ? inv  : sneg;
    c          = (kv >= 0.f) ? sneg : inv;
    float eh   = __expf(-fabsf(ht));
    float gneg = eh / (1.0f + eh);
    float g    = (ht >= 0.f) ? (ht + 0.5f) : gneg;
    v = z * g;
}

// ---------------- K0a: x -> fp16 -------------------------------------------
__global__ void xhalf_kernel(const float* __restrict__ in) {
    int i = blockIdx.x * blockDim.x + threadIdx.x;   // float4 index
    float4 u = reinterpret_cast<const float4*>(in)[i];
    __half2 lo = __floats2half2_rn(u.x, u.y);
    __half2 hi = __floats2half2_rn(u.z, u.w);
    uint2 o;
    o.x = *reinterpret_cast<unsigned*>(&lo);
    o.y = *reinterpret_cast<unsigned*>(&hi);
    *reinterpret_cast<uint2*>(g_xh + (size_t)i * 4) = o;
}

// ---------------- K0b: transpose + fp16 W: g_wh[n][k] = h(W[k][n]) ---------
__global__ void transpose_w_kernel(const float* __restrict__ Wm) {
    __shared__ float t[32][33];
    int n0 = blockIdx.x * 32, k0 = blockIdx.y * 32;
    int tx = threadIdx.x, ty = threadIdx.y;
    #pragma unroll
    for (int i = ty; i < 32; i += 8)
        t[i][tx] = Wm[(size_t)(k0 + i) * N2 + n0 + tx];
    __syncthreads();
    #pragma unroll
    for (int j = ty; j < 32; j += 8)
        g_wh[(size_t)(n0 + j) * D + k0 + tx] = __float2half_rn(t[tx][j]);
}

// ---------------- K1: fp16 mma.sync GEMM + gates + fused chunk summary -----
// CTA tile: 128 m-rows x 128 paired cols (h col j and k col D+j together).
// B smem rows 0..127 = h cols [nb, nb+128), rows 128..255 = k cols.
// 8 warps: warp_m in {0,1} (64 rows = one time-chunk), warp_n in {0..3}.
// BK=64 halves (128B rows, SW128 swizzle), 4-stage cp.async, ldmatrix frags.
static constexpr int BM = 128;
static constexpr int BNP = 128;              // paired columns per CTA
static constexpr int BK = 64;                // halves per stage row
static constexpr int STAGES = 4;
static constexpr int KT = D / BK;            // 16
static constexpr int ASTAGE = BM * 128;              // 16 KB
static constexpr int BSTAGE = 2 * BNP * 128;         // 32 KB
static constexpr int STAGE_BYTES = ASTAGE + BSTAGE;  // 48 KB
static constexpr int SMEM_TOTAL = STAGES * STAGE_BYTES;  // 192 KB

__global__ __launch_bounds__(256, 1)
void gemm_gate_kernel(const float* __restrict__ bias) {
    extern __shared__ __align__(1024) unsigned char smem_buf[];
    const unsigned sbase = smem_u32(smem_buf);
    const int tid  = threadIdx.x;
    const int wid  = tid >> 5;
    const int lane = tid & 31;
    const int warp_m = wid & 1;
    const int warp_n = wid >> 1;
    const int qr = lane >> 2, qc = lane & 3;

    const int mb = blockIdx.y * BM;
    const int nb = blockIdx.x * BNP;
    const __half* xA = g_xh + (size_t)mb * D;

    // ---- per-lane ldmatrix address components ----
    const unsigned rA7 = (unsigned)(lane & 7);
    const unsigned sXor = rA7 << 4;                    // swizzle XOR term
    const unsigned hA16 = (unsigned)(lane & 16);       // A: k-half (16B) select
    unsigned offA[4];
    #pragma unroll
    for (int mt = 0; mt < 4; mt++) {
        unsigned row = (unsigned)(warp_m * 64 + mt * 16) + rA7 + ((lane & 8) ? 8u : 0u);
        offA[mt] = row * 128u;
    }
    const unsigned hB16 = (unsigned)((lane & 8) << 1); // B: k-half select
    unsigned offBh[2], offBk[2];
    #pragma unroll
    for (int p = 0; p < 2; p++) {
        unsigned row = (unsigned)(warp_n * 32 + p * 16) + rA7 + ((lane & 16) ? 8u : 0u);
        offBh[p] = row * 128u;
        offBk[p] = offBh[p] + (unsigned)(BNP * 128);
    }

    float acc[4][8][4];
    #pragma unroll
    for (int mt = 0; mt < 4; mt++)
        #pragma unroll
        for (int nt = 0; nt < 8; nt++)
            #pragma unroll
            for (int j = 0; j < 4; j++) acc[mt][nt][j] = 0.f;

    auto load_stage = [&](int s, int kiter) {
        const int k0 = kiter * BK;
        const unsigned abase = sbase + (unsigned)s * STAGE_BYTES;
        const unsigned bbase = abase + ASTAGE;
        // A: 128 rows x 8 chunks of 16B (8 halves)
        #pragma unroll
        for (int i = 0; i < 4; i++) {
            int id = tid + i * 256;
            int r = id >> 3, c = id & 7;
            unsigned off = (unsigned)r * 128u + (((unsigned)c * 16u) ^ (((unsigned)r & 7u) << 4));
            cp16(abase + off, xA + (size_t)r * D + k0 + c * 8);
        }
        // B: 256 rows (128 h + 128 k) x 8 chunks
        #pragma unroll
        for (int i = 0; i < 8; i++) {
            int id = tid + i * 256;
            int r = id >> 3, c = id & 7;
            int wrow = (r < BNP) ? (nb + r) : (D + nb + (r - BNP));
            unsigned off = (unsigned)r * 128u + (((unsigned)c * 16u) ^ (((unsigned)r & 7u) << 4));
            cp16(bbase + off, g_wh + (size_t)wrow * D + k0 + c * 8);
        }
    };

    auto compute_stage = [&](int s) {
        const unsigned abase = sbase + (unsigned)s * STAGE_BYTES;
        const unsigned bbase = abase + ASTAGE;
        #pragma unroll
        for (int kk = 0; kk < 4; kk++) {          // 4 x k16 per 128B row
            const unsigned tA = (((unsigned)kk << 5) | hA16) ^ sXor;
            const unsigned tB = (((unsigned)kk << 5) | hB16) ^ sXor;
            uint32_t a[4][4];
            #pragma unroll
            for (int mt = 0; mt < 4; mt++) ldsm_x4(a[mt], abase + offA[mt] + tA);
            uint32_t bh[2][4], bk[2][4];
            #pragma unroll
            for (int p = 0; p < 2; p++) {
                ldsm_x4(bh[p], bbase + offBh[p] + tB);
                ldsm_x4(bk[p], bbase + offBk[p] + tB);
            }
            #pragma unroll
            for (int mt = 0; mt < 4; mt++) {
                #pragma unroll
                for (int p = 0; p < 2; p++) {
                    mma_f16(acc[mt][p * 2    ], a[mt], bh[p][0], bh[p][1]);
                    mma_f16(acc[mt][p * 2 + 1], a[mt], bh[p][2], bh[p][3]);
                    mma_f16(acc[mt][4 + p * 2    ], a[mt], bk[p][0], bk[p][1]);
                    mma_f16(acc[mt][4 + p * 2 + 1], a[mt], bk[p][2], bk[p][3]);
                }
            }
        }
    };

    // prologue: stages 0..2
    load_stage(0, 0); cp_commit();
    load_stage(1, 1); cp_commit();
    load_stage(2, 2); cp_commit();

    for (int ks = 0; ks < KT; ks++) {
        cp_wait<STAGES - 2>();
        __syncthreads();
        if (ks + STAGES - 1 < KT) load_stage((ks + STAGES - 1) % STAGES, ks + STAGES - 1);
        cp_commit();
        compute_stage(ks % STAGES);
    }

    // drain pipeline; smem is reused below for the chunk-summary staging
    cp_wait<0>();
    __syncthreads();

    // per-warp staging: [64 rows][34 cols] for c and v (17408 B/warp, 139 KB total)
    float* cs = reinterpret_cast<float*>(smem_buf) + (size_t)wid * (2 * 64 * 34);
    float* vs = cs + 64 * 34;

    // ---- epilogue: pair (h, k), gates, write c,v + stage to smem ----
    #pragma unroll
    for (int nt = 0; nt < 4; nt++) {
        const int colIdx = nt * 8 + qc * 2;            // 0..31 within warp slab
        const int col = nb + warp_n * 32 + colIdx;
        const float2 bh2 = *reinterpret_cast<const float2*>(bias + col);
        const float2 bk2 = *reinterpret_cast<const float2*>(bias + D + col);
        #pragma unroll
        for (int mt = 0; mt < 4; mt++) {
            #pragma unroll
            for (int j2 = 0; j2 < 2; j2++) {
                const int rl = mt * 16 + j2 * 8 + qr;  // 0..63 within chunk
                const int row = mb + warp_m * 64 + rl;
                float h0 = acc[mt][nt][j2 * 2 + 0] + bh2.x;
                float h1 = acc[mt][nt][j2 * 2 + 1] + bh2.y;
                float k0 = acc[mt][nt + 4][j2 * 2 + 0] + bk2.x;
                float k1 = acc[mt][nt + 4][j2 * 2 + 1] + bk2.y;
                float c0, v0, c1, v1;
                gate_act(h0, k0, c0, v0);
                gate_act(h1, k1, c1, v1);
                const size_t o = (size_t)row * D + col;
                *reinterpret_cast<float2*>(g_c + o) = make_float2(c0, c1);
                *reinterpret_cast<float2*>(g_v + o) = make_float2(v0, v1);
                cs[rl * 34 + colIdx]     = c0;
                cs[rl * 34 + colIdx + 1] = c1;
                vs[rl * 34 + colIdx]     = v0;
                vs[rl * 34 + colIdx + 1] = v1;
            }
        }
    }
    __syncwarp();

    // ---- fused chunk summary: P = prod c, S = local scan over 64 rows ----
    {
        float P = 1.f, S = 0.f;
        #pragma unroll 8
        for (int r = 0; r < 64; r++) {
            float c = cs[r * 34 + lane];
            float v = vs[r * 34 + lane];
            S = fmaf(c, S, v);
            P *= c;
        }
        const int bc = (mb + warp_m * 64) >> 6;        // == b*NCH + chunk
        const int col = nb + warp_n * 32 + lane;
        g_P[(size_t)bc * D + col] = P;
        g_S[(size_t)bc * D + col] = S;
    }
}

// ---------------- K3: sequential scan across chunks (prefetch depth 2) -----
__global__ __launch_bounds__(256)
void chunk_scan_kernel() {
    int b  = blockIdx.x;
    int d4 = threadIdx.x;
    size_t idx0 = (size_t)(b * NCH) * D + d4 * 4;
    float4 h  = make_float4(0.f, 0.f, 0.f, 0.f);
    float4 P0 = *reinterpret_cast<const float4*>(g_P + idx0);
    float4 S0 = *reinterpret_cast<const float4*>(g_S + idx0);
    float4 P1 = *reinterpret_cast<const float4*>(g_P + idx0 + D);
    float4 S1 = *reinterpret_cast<const float4*>(g_S + idx0 + D);
    for (int ch = 0; ch < NCH; ch++) {
        float4 Pn, Sn;
        if (ch + 2 < NCH) {
            Pn = *reinterpret_cast<const float4*>(g_P + idx0 + (size_t)(ch + 2) * D);
            Sn = *reinterpret_cast<const float4*>(g_S + idx0 + (size_t)(ch + 2) * D);
        }
        *reinterpret_cast<float4*>(g_h0 + idx0 + (size_t)ch * D) = h;
        h.x = fmaf(P0.x, h.x, S0.x); h.y = fmaf(P0.y, h.y, S0.y);
        h.z = fmaf(P0.z, h.z, S0.z); h.w = fmaf(P0.w, h.w, S0.w);
        P0 = P1; S0 = S1; P1 = Pn; S1 = Sn;
    }
}

// ---------------- K4: apply scan + residual + LayerNorm (float4+prefetch) --
__global__ __launch_bounds__(256)
void apply_ln_kernel(const float* __restrict__ x,
                     const float* __restrict__ gamma,
                     const float* __restrict__ beta,
                     float* __restrict__ out) {
    __shared__ float red[16];
    int bc = blockIdx.x;
    int tid = threadIdx.x;
    int b  = bc / NCH, ch = bc % NCH;
    int lane = tid & 31, w = tid >> 5;
    size_t d4 = (size_t)tid * 4;

    float4 h = *reinterpret_cast<const float4*>(g_h0 + (size_t)bc * D + d4);
    float4 gm = *reinterpret_cast<const float4*>(gamma + d4);
    float4 bt = *reinterpret_cast<const float4*>(beta + d4);
    size_t base = ((size_t)b * T + (size_t)ch * CHUNK) * D + d4;

    float4 c4 = *reinterpret_cast<const float4*>(g_c + base);
    float4 v4 = *reinterpret_cast<const float4*>(g_v + base);
    float4 x4 = *reinterpret_cast<const float4*>(x + base);

    for (int i = 0; i < CHUNK; i++) {
        float4 cn, vn, xn;
        if (i + 1 < CHUNK) {
            size_t nb2 = base + (size_t)(i + 1) * D;
            cn = *reinterpret_cast<const float4*>(g_c + nb2);
            vn = *reinterpret_cast<const float4*>(g_v + nb2);
            xn = *reinterpret_cast<const float4*>(x + nb2);
        }
        h.x = fmaf(c4.x, h.x, v4.x); h.y = fmaf(c4.y, h.y, v4.y);
        h.z = fmaf(c4.z, h.z, v4.z); h.w = fmaf(c4.w, h.w, v4.w);
        float4 y;
        y.x = x4.x + h.x; y.y = x4.y + h.y; y.z = x4.z + h.z; y.w = x4.w + h.w;
        float s  = y.x + y.y + y.z + y.w;
        float sq = y.x * y.x + y.y * y.y + y.z * y.z + y.w * y.w;
        #pragma unroll
        for (int o = 16; o > 0; o >>= 1) {
            s  += __shfl_xor_sync(0xffffffffu, s,  o);
            sq += __shfl_xor_sync(0xffffffffu, sq, o);
        }
        if (lane == 0) { red[w] = s; red[8 + w] = sq; }
        __syncthreads();
        if (tid == 0) {
            float s2 = 0.f, q2 = 0.f;
            #pragma unroll
            for (int k = 0; k < 8; k++) { s2 += red[k]; q2 += red[8 + k]; }
            red[0] = s2; red[8] = q2;
        }
        __syncthreads();
        float mu  = red[0] * (1.0f / D);
        float var = red[8] * (1.0f / D) - mu * mu;
        float inv = rsqrtf(var + 1e-6f);
        float4 o4;
        o4.x = (y.x - mu) * inv * gm.x + bt.x;
        o4.y = (y.y - mu) * inv * gm.y + bt.y;
        o4.z = (y.z - mu) * inv * gm.z + bt.z;
        o4.w = (y.w - mu) * inv * gm.w + bt.w;
        *reinterpret_cast<float4*>(out + base + (size_t)i * D) = o4;
        c4 = cn; v4 = vn; x4 = xn;
        __syncthreads();   // red reuse
    }
}

// ---------------- launch ----------------------------------------------------
extern "C" void kernel_launch(void* const* d_in, const int* in_sizes, int n_in,
                              void* d_out, int out_size) {
    const float* x     = (const float*)d_in[0];
    const float* W     = (const float*)d_in[1];
    const float* bias  = (const float*)d_in[2];
    const float* gamma = (const float*)d_in[3];
    const float* beta  = (const float*)d_in[4];
    float* out = (float*)d_out;
    (void)in_sizes; (void)n_in; (void)out_size;

    // K0: operand prep (fp16)
    xhalf_kernel<<<(M * D / 4) / 256, 256>>>(x);
    transpose_w_kernel<<<dim3(N2 / 32, D / 32), dim3(32, 8)>>>(W);

    // K1: fp16 mma.sync GEMM + gates + fused chunk summary
    static bool attr_set = false;
    if (!attr_set) {
        cudaFuncSetAttribute(gemm_gate_kernel,
                             cudaFuncAttributeMaxDynamicSharedMemorySize, SMEM_TOTAL);
        attr_set = true;
    }
    gemm_gate_kernel<<<dim3(D / BNP, M / BM), 256, SMEM_TOTAL>>>(bias);

    // K3: cross-chunk scan
    chunk_scan_kernel<<<B, 256>>>();

    // K4: apply + residual + LayerNorm
    apply_ln_kernel<<<B * NCH, 256>>>(x, gamma, beta, out);
}

// round 5
// speedup vs baseline: 1.9890x; 1.0262x over previous
#include <cuda_runtime.h>
#include <cuda_fp16.h>
#include <cstdint>
#include <cstddef>

#define DEV_INLINE __device__ __forceinline__

// Problem shape (fixed by setup_inputs)
static constexpr int B  = 8;
static constexpr int T  = 4096;
static constexpr int D  = 1024;
static constexpr int M  = B * T;       // 32768
static constexpr int N2 = 2 * D;       // 2048
static constexpr int CHUNK = 64;
static constexpr int NCH   = T / CHUNK; // 64

// ---------------- scratch (static __device__ arrays) -----------------------
__device__ __half g_c [(size_t)M * D];     // per-step coefficient (fp16)
__device__ __half g_v [(size_t)M * D];     // per-step value (fp16)
__device__ __half g_xh[(size_t)M * D];     // fp16 x
__device__ __half g_wh[(size_t)N2 * D];    // fp16 transposed W  [n][k]
__device__ float  g_P [B * NCH * D];
__device__ float  g_S [B * NCH * D];
__device__ float  g_h0[B * NCH * D];

// ---------------- helpers --------------------------------------------------
DEV_INLINE unsigned smem_u32(const void* p) {
    return (unsigned)__cvta_generic_to_shared(p);
}
DEV_INLINE void cp16(unsigned dst, const void* src) {
    asm volatile("cp.async.cg.shared.global [%0], [%1], 16;"
                 :: "r"(dst), "l"(src));
}
DEV_INLINE void cp_commit() { asm volatile("cp.async.commit_group;"); }
template<int N> DEV_INLINE void cp_wait() {
    asm volatile("cp.async.wait_group %0;" :: "n"(N));
}

DEV_INLINE void ldsm_x4(uint32_t r[4], unsigned addr) {
    asm volatile("ldmatrix.sync.aligned.m8n8.x4.shared.b16 {%0,%1,%2,%3}, [%4];"
                 : "=r"(r[0]), "=r"(r[1]), "=r"(r[2]), "=r"(r[3]) : "r"(addr));
}

DEV_INLINE void mma_f16(float acc[4], const uint32_t a[4], uint32_t b0, uint32_t b1) {
    asm volatile(
        "mma.sync.aligned.m16n8k16.row.col.f32.f16.f16.f32 "
        "{%0,%1,%2,%3}, {%4,%5,%6,%7}, {%8,%9}, {%0,%1,%2,%3};\n"
        : "+f"(acc[0]), "+f"(acc[1]), "+f"(acc[2]), "+f"(acc[3])
        : "r"(a[0]), "r"(a[1]), "r"(a[2]), "r"(a[3]), "r"(b0), "r"(b1));
}

// c = sigmoid(-k), v = sigmoid(k) * g(ht);  g(x) = x+0.5 (x>=0) else sigmoid(x)
DEV_INLINE void gate_act(float ht, float kv, float& c, float& v) {
    float ek   = __expf(-fabsf(kv));
    float inv  = 1.0f / (1.0f + ek);
    float sneg = ek * inv;
    float z    = (kv >= 0.f) ? inv  : sneg;
    c          = (kv >= 0.f) ? sneg : inv;
    float eh   = __expf(-fabsf(ht));
    float gneg = eh / (1.0f + eh);
    float g    = (ht >= 0.f) ? (ht + 0.5f) : gneg;
    v = z * g;
}

DEV_INLINE float4 ld_half4(const __half* p) {
    uint2 u = *reinterpret_cast<const uint2*>(p);
    __half2 h0 = *reinterpret_cast<__half2*>(&u.x);
    __half2 h1 = *reinterpret_cast<__half2*>(&u.y);
    float2 f0 = __half22float2(h0);
    float2 f1 = __half22float2(h1);
    return make_float4(f0.x, f0.y, f1.x, f1.y);
}

// ---------------- K0a: x -> fp16 -------------------------------------------
__global__ void xhalf_kernel(const float* __restrict__ in) {
    int i = blockIdx.x * blockDim.x + threadIdx.x;   // float4 index
    float4 u = reinterpret_cast<const float4*>(in)[i];
    __half2 lo = __floats2half2_rn(u.x, u.y);
    __half2 hi = __floats2half2_rn(u.z, u.w);
    uint2 o;
    o.x = *reinterpret_cast<unsigned*>(&lo);
    o.y = *reinterpret_cast<unsigned*>(&hi);
    *reinterpret_cast<uint2*>(g_xh + (size_t)i * 4) = o;
}

// ---------------- K0b: transpose + fp16 W: g_wh[n][k] = h(W[k][n]) ---------
__global__ void transpose_w_kernel(const float* __restrict__ Wm) {
    __shared__ float t[32][33];
    int n0 = blockIdx.x * 32, k0 = blockIdx.y * 32;
    int tx = threadIdx.x, ty = threadIdx.y;
    #pragma unroll
    for (int i = ty; i < 32; i += 8)
        t[i][tx] = Wm[(size_t)(k0 + i) * N2 + n0 + tx];
    __syncthreads();
    #pragma unroll
    for (int j = ty; j < 32; j += 8)
        g_wh[(size_t)(n0 + j) * D + k0 + tx] = __float2half_rn(t[tx][j]);
}

// ---------------- K1: fp16 mma.sync GEMM + gates + fused chunk summary -----
static constexpr int BM = 128;
static constexpr int BNP = 128;              // paired columns per CTA
static constexpr int BK = 64;                // halves per stage row
static constexpr int STAGES = 4;
static constexpr int KT = D / BK;            // 16
static constexpr int ASTAGE = BM * 128;              // 16 KB
static constexpr int BSTAGE = 2 * BNP * 128;         // 32 KB
static constexpr int STAGE_BYTES = ASTAGE + BSTAGE;  // 48 KB
static constexpr int SMEM_TOTAL = STAGES * STAGE_BYTES;  // 192 KB

__global__ __launch_bounds__(256, 1)
void gemm_gate_kernel(const float* __restrict__ bias) {
    extern __shared__ __align__(1024) unsigned char smem_buf[];
    const unsigned sbase = smem_u32(smem_buf);
    const int tid  = threadIdx.x;
    const int wid  = tid >> 5;
    const int lane = tid & 31;
    const int warp_m = wid & 1;
    const int warp_n = wid >> 1;
    const int qr = lane >> 2, qc = lane & 3;

    const int mb = blockIdx.y * BM;
    const int nb = blockIdx.x * BNP;
    const __half* xA = g_xh + (size_t)mb * D;

    // ---- per-lane ldmatrix address components ----
    const unsigned rA7 = (unsigned)(lane & 7);
    const unsigned sXor = rA7 << 4;                    // swizzle XOR term
    const unsigned hA16 = (unsigned)(lane & 16);       // A: k-half (16B) select
    unsigned offA[4];
    #pragma unroll
    for (int mt = 0; mt < 4; mt++) {
        unsigned row = (unsigned)(warp_m * 64 + mt * 16) + rA7 + ((lane & 8) ? 8u : 0u);
        offA[mt] = row * 128u;
    }
    const unsigned hB16 = (unsigned)((lane & 8) << 1); // B: k-half select
    unsigned offBh[2], offBk[2];
    #pragma unroll
    for (int p = 0; p < 2; p++) {
        unsigned row = (unsigned)(warp_n * 32 + p * 16) + rA7 + ((lane & 16) ? 8u : 0u);
        offBh[p] = row * 128u;
        offBk[p] = offBh[p] + (unsigned)(BNP * 128);
    }

    float acc[4][8][4];
    #pragma unroll
    for (int mt = 0; mt < 4; mt++)
        #pragma unroll
        for (int nt = 0; nt < 8; nt++)
            #pragma unroll
            for (int j = 0; j < 4; j++) acc[mt][nt][j] = 0.f;

    auto load_stage = [&](int s, int kiter) {
        const int k0 = kiter * BK;
        const unsigned abase = sbase + (unsigned)s * STAGE_BYTES;
        const unsigned bbase = abase + ASTAGE;
        // A: 128 rows x 8 chunks of 16B (8 halves)
        #pragma unroll
        for (int i = 0; i < 4; i++) {
            int id = tid + i * 256;
            int r = id >> 3, c = id & 7;
            unsigned off = (unsigned)r * 128u + (((unsigned)c * 16u) ^ (((unsigned)r & 7u) << 4));
            cp16(abase + off, xA + (size_t)r * D + k0 + c * 8);
        }
        // B: 256 rows (128 h + 128 k) x 8 chunks
        #pragma unroll
        for (int i = 0; i < 8; i++) {
            int id = tid + i * 256;
            int r = id >> 3, c = id & 7;
            int wrow = (r < BNP) ? (nb + r) : (D + nb + (r - BNP));
            unsigned off = (unsigned)r * 128u + (((unsigned)c * 16u) ^ (((unsigned)r & 7u) << 4));
            cp16(bbase + off, g_wh + (size_t)wrow * D + k0 + c * 8);
        }
    };

    auto compute_stage = [&](int s) {
        const unsigned abase = sbase + (unsigned)s * STAGE_BYTES;
        const unsigned bbase = abase + ASTAGE;
        #pragma unroll
        for (int kk = 0; kk < 4; kk++) {          // 4 x k16 per 128B row
            const unsigned tA = (((unsigned)kk << 5) | hA16) ^ sXor;
            const unsigned tB = (((unsigned)kk << 5) | hB16) ^ sXor;
            uint32_t a[4][4];
            #pragma unroll
            for (int mt = 0; mt < 4; mt++) ldsm_x4(a[mt], abase + offA[mt] + tA);
            uint32_t bh[2][4], bk[2][4];
            #pragma unroll
            for (int p = 0; p < 2; p++) {
                ldsm_x4(bh[p], bbase + offBh[p] + tB);
                ldsm_x4(bk[p], bbase + offBk[p] + tB);
            }
            #pragma unroll
            for (int mt = 0; mt < 4; mt++) {
                #pragma unroll
                for (int p = 0; p < 2; p++) {
                    mma_f16(acc[mt][p * 2    ], a[mt], bh[p][0], bh[p][1]);
                    mma_f16(acc[mt][p * 2 + 1], a[mt], bh[p][2], bh[p][3]);
                    mma_f16(acc[mt][4 + p * 2    ], a[mt], bk[p][0], bk[p][1]);
                    mma_f16(acc[mt][4 + p * 2 + 1], a[mt], bk[p][2], bk[p][3]);
                }
            }
        }
    };

    // prologue: stages 0..2
    load_stage(0, 0); cp_commit();
    load_stage(1, 1); cp_commit();
    load_stage(2, 2); cp_commit();

    for (int ks = 0; ks < KT; ks++) {
        cp_wait<STAGES - 2>();
        __syncthreads();
        if (ks + STAGES - 1 < KT) load_stage((ks + STAGES - 1) % STAGES, ks + STAGES - 1);
        cp_commit();
        compute_stage(ks % STAGES);
    }

    // drain pipeline; smem is reused below for the chunk-summary staging
    cp_wait<0>();
    __syncthreads();

    // per-warp staging: [64 rows][34 cols] for c and v (17408 B/warp, 139 KB)
    float* cs = reinterpret_cast<float*>(smem_buf) + (size_t)wid * (2 * 64 * 34);
    float* vs = cs + 64 * 34;

    // ---- epilogue: pair (h, k), gates, fp16 store + stage rounded values ----
    #pragma unroll
    for (int nt = 0; nt < 4; nt++) {
        const int colIdx = nt * 8 + qc * 2;            // 0..31 within warp slab
        const int col = nb + warp_n * 32 + colIdx;
        const float2 bh2 = *reinterpret_cast<const float2*>(bias + col);
        const float2 bk2 = *reinterpret_cast<const float2*>(bias + D + col);
        #pragma unroll
        for (int mt = 0; mt < 4; mt++) {
            #pragma unroll
            for (int j2 = 0; j2 < 2; j2++) {
                const int rl = mt * 16 + j2 * 8 + qr;  // 0..63 within chunk
                const int row = mb + warp_m * 64 + rl;
                float h0 = acc[mt][nt][j2 * 2 + 0] + bh2.x;
                float h1 = acc[mt][nt][j2 * 2 + 1] + bh2.y;
                float k0 = acc[mt][nt + 4][j2 * 2 + 0] + bk2.x;
                float k1 = acc[mt][nt + 4][j2 * 2 + 1] + bk2.y;
                float c0, v0, c1, v1;
                gate_act(h0, k0, c0, v0);
                gate_act(h1, k1, c1, v1);
                __half2 ch = __floats2half2_rn(c0, c1);
                __half2 vh = __floats2half2_rn(v0, v1);
                const size_t o = (size_t)row * D + col;
                *reinterpret_cast<__half2*>(g_c + o) = ch;
                *reinterpret_cast<__half2*>(g_v + o) = vh;
                // stage the fp16-rounded values so P,S match the recurrence
                float2 cr = __half22float2(ch);
                float2 vr = __half22float2(vh);
                cs[rl * 34 + colIdx]     = cr.x;
                cs[rl * 34 + colIdx + 1] = cr.y;
                vs[rl * 34 + colIdx]     = vr.x;
                vs[rl * 34 + colIdx + 1] = vr.y;
            }
        }
    }
    __syncwarp();

    // ---- fused chunk summary: P = prod c, S = local scan over 64 rows ----
    {
        float P = 1.f, S = 0.f;
        #pragma unroll 8
        for (int r = 0; r < 64; r++) {
            float c = cs[r * 34 + lane];
            float v = vs[r * 34 + lane];
            S = fmaf(c, S, v);
            P *= c;
        }
        const int bc = (mb + warp_m * 64) >> 6;        // == b*NCH + chunk
        const int col = nb + warp_n * 32 + lane;
        g_P[(size_t)bc * D + col] = P;
        g_S[(size_t)bc * D + col] = S;
    }
}

// ---------------- K3: sequential scan across chunks ------------------------
// grid (B, 4): each block scans 256 d-columns of one batch; 1 float/thread.
__global__ __launch_bounds__(256)
void chunk_scan_kernel() {
    int b  = blockIdx.x;
    int d  = blockIdx.y * 256 + threadIdx.x;
    size_t idx0 = (size_t)(b * NCH) * D + d;
    float h  = 0.f;
    float P0 = g_P[idx0];
    float S0 = g_S[idx0];
    float P1 = g_P[idx0 + D];
    float S1 = g_S[idx0 + D];
    for (int ch = 0; ch < NCH; ch++) {
        float Pn = 0.f, Sn = 0.f;
        if (ch + 2 < NCH) {
            Pn = g_P[idx0 + (size_t)(ch + 2) * D];
            Sn = g_S[idx0 + (size_t)(ch + 2) * D];
        }
        g_h0[idx0 + (size_t)ch * D] = h;
        h = fmaf(P0, h, S0);
        P0 = P1; S0 = S1; P1 = Pn; S1 = Sn;
    }
}

// ---------------- K4: apply scan + residual + LayerNorm ---------------------
__global__ __launch_bounds__(256)
void apply_ln_kernel(const float* __restrict__ x,
                     const float* __restrict__ gamma,
                     const float* __restrict__ beta,
                     float* __restrict__ out) {
    __shared__ float red[16];
    int bc = blockIdx.x;
    int tid = threadIdx.x;
    int b  = bc / NCH, ch = bc % NCH;
    int lane = tid & 31, w = tid >> 5;
    size_t d4 = (size_t)tid * 4;

    float4 h = *reinterpret_cast<const float4*>(g_h0 + (size_t)bc * D + d4);
    float4 gm = *reinterpret_cast<const float4*>(gamma + d4);
    float4 bt = *reinterpret_cast<const float4*>(beta + d4);
    size_t base = ((size_t)b * T + (size_t)ch * CHUNK) * D + d4;

    float4 c4 = ld_half4(g_c + base);
    float4 v4 = ld_half4(g_v + base);
    float4 x4 = *reinterpret_cast<const float4*>(x + base);

    for (int i = 0; i < CHUNK; i++) {
        float4 cn, vn, xn;
        if (i + 1 < CHUNK) {
            size_t nb2 = base + (size_t)(i + 1) * D;
            cn = ld_half4(g_c + nb2);
            vn = ld_half4(g_v + nb2);
            xn = *reinterpret_cast<const float4*>(x + nb2);
        }
        h.x = fmaf(c4.x, h.x, v4.x); h.y = fmaf(c4.y, h.y, v4.y);
        h.z = fmaf(c4.z, h.z, v4.z); h.w = fmaf(c4.w, h.w, v4.w);
        float4 y;
        y.x = x4.x + h.x; y.y = x4.y + h.y; y.z = x4.z + h.z; y.w = x4.w + h.w;
        float s  = y.x + y.y + y.z + y.w;
        float sq = y.x * y.x + y.y * y.y + y.z * y.z + y.w * y.w;
        #pragma unroll
        for (int o = 16; o > 0; o >>= 1) {
            s  += __shfl_xor_sync(0xffffffffu, s,  o);
            sq += __shfl_xor_sync(0xffffffffu, sq, o);
        }
        if (lane == 0) { red[w] = s; red[8 + w] = sq; }
        __syncthreads();
        if (tid == 0) {
            float s2 = 0.f, q2 = 0.f;
            #pragma unroll
            for (int k = 0; k < 8; k++) { s2 += red[k]; q2 += red[8 + k]; }
            red[0] = s2; red[8] = q2;
        }
        __syncthreads();
        float mu  = red[0] * (1.0f / D);
        float var = red[8] * (1.0f / D) - mu * mu;
        float inv = rsqrtf(var + 1e-6f);
        float4 o4;
        o4.x = (y.x - mu) * inv * gm.x + bt.x;
        o4.y = (y.y - mu) * inv * gm.y + bt.y;
        o4.z = (y.z - mu) * inv * gm.z + bt.z;
        o4.w = (y.w - mu) * inv * gm.w + bt.w;
        *reinterpret_cast<float4*>(out + base + (size_t)i * D) = o4;
        c4 = cn; v4 = vn; x4 = xn;
        __syncthreads();   // red reuse
    }
}

// ---------------- launch ----------------------------------------------------
extern "C" void kernel_launch(void* const* d_in, const int* in_sizes, int n_in,
                              void* d_out, int out_size) {
    const float* x     = (const float*)d_in[0];
    const float* W     = (const float*)d_in[1];
    const float* bias  = (const float*)d_in[2];
    const float* gamma = (const float*)d_in[3];
    const float* beta  = (const float*)d_in[4];
    float* out = (float*)d_out;
    (void)in_sizes; (void)n_in; (void)out_size;

    // K0: operand prep (fp16)
    xhalf_kernel<<<(M * D / 4) / 256, 256>>>(x);
    transpose_w_kernel<<<dim3(N2 / 32, D / 32), dim3(32, 8)>>>(W);

    // K1: fp16 mma.sync GEMM + gates + fused chunk summary
    static bool attr_set = false;
    if (!attr_set) {
        cudaFuncSetAttribute(gemm_gate_kernel,
                             cudaFuncAttributeMaxDynamicSharedMemorySize, SMEM_TOTAL);
        attr_set = true;
    }
    gemm_gate_kernel<<<dim3(D / BNP, M / BM), 256, SMEM_TOTAL>>>(bias);

    // K3: cross-chunk scan
    chunk_scan_kernel<<<dim3(B, 4), 256>>>();

    // K4: apply + residual + LayerNorm
    apply_ln_kernel<<<B * NCH, 256>>>(x, gamma, beta, out);
}